// round 2
// baseline (speedup 1.0000x reference)
#include <cuda_runtime.h>
#include <cuda_bf16.h>

#define LMAX 8

// ---------------------------------------------------------------------------
// Compile-time math: factorial + Newton-iteration sqrt, both constexpr so the
// 54 normalization constants become SASS immediates (forced via template
// parameters + constexpr locals below — guaranteed compile-time evaluation).
// ---------------------------------------------------------------------------
__host__ __device__ constexpr double cfact(int n) {
    double r = 1.0;
    for (int i = 2; i <= n; ++i) r *= (double)i;
    return r;
}

__host__ __device__ constexpr double csqrt_(double x) {
    // Newton iteration; converges for all x in (0, ~20] used here.
    double g = x < 1.0 ? 1.0 : x;
    for (int i = 0; i < 100; ++i) g = 0.5 * (g + x / g);
    return g;
}

constexpr double PI_D = 3.141592653589793238462643383279502884;

__host__ __device__ constexpr float Fcoef(int l, int m) {
    double v = csqrt_(((2.0 * l + 1.0) / (2.0 * PI_D)) * (cfact(l - m) / cfact(l + m)));
    return (float)((m & 1) ? -v : v);
}

__host__ __device__ constexpr float Acoef(int l) {
    return (float)csqrt_((2.0 * l + 1.0) / (4.0 * PI_D));
}

// ---------------------------------------------------------------------------
// Emit the 2l+1 outputs of degree L. Coefficients are constexpr locals bound
// to template parameters -> mandatory compile-time evaluation -> immediates.
// Output layout: block l starts at element offset l*l*N, row-major [N, 2l+1],
// column order m = -l..-1 (sin), 0, 1..l (cos).
// ---------------------------------------------------------------------------
template<int L, int M>
__device__ __forceinline__ void emit_ms(float* __restrict__ o,
                                        const float (&Q)[LMAX + 1][LMAX + 1],
                                        const float (&s)[LMAX + 1],
                                        const float (&c)[LMAX + 1]) {
    if constexpr (M >= 1) {
        constexpr float f = Fcoef(L, M);
        float fq = f * Q[L][M];
        o[L - M] = fq * s[M];
        o[L + M] = fq * c[M];
        emit_ms<L, M - 1>(o, Q, s, c);
    }
}

template<int L>
__device__ __forceinline__ void emit_l(float* __restrict__ out,
                                       long long N, long long n,
                                       const float (&Q)[LMAX + 1][LMAX + 1],
                                       const float (&s)[LMAX + 1],
                                       const float (&c)[LMAX + 1]) {
    float* o = out + (long long)(L * L) * N + n * (long long)(2 * L + 1);
    constexpr float a = Acoef(L);
    o[L] = a * Q[L][0];
    emit_ms<L, L>(o, Q, s, c);
}

// ---------------------------------------------------------------------------
// Kernel: one thread per point. Fully unrolled recurrences; all array indices
// are compile-time constants after unrolling, so c/s/Q live in registers.
// ---------------------------------------------------------------------------
__global__ void __launch_bounds__(256)
solid_harmonics_kernel(const float* __restrict__ R, float* __restrict__ out, int N) {
    int n = blockIdx.x * blockDim.x + threadIdx.x;
    if (n >= N) return;

    float x = R[3 * n + 0];
    float y = R[3 * n + 1];
    float z = R[3 * n + 2];
    float r2 = x * x + y * y + z * z;

    // Azimuthal chain: c[m] = Re[(x+iy)^m], s[m] = Im[(x+iy)^m]
    float c[LMAX + 1], s[LMAX + 1];
    c[0] = 1.0f;
    s[0] = 0.0f;
#pragma unroll
    for (int m = 1; m <= LMAX; ++m) {
        c[m] = x * c[m - 1] - y * s[m - 1];
        s[m] = x * s[m - 1] + y * c[m - 1];
    }

    // Q(l,m) recurrence (solid-harmonic associated Legendre, sphericart form)
    float Q[LMAX + 1][LMAX + 1];
    Q[0][0] = 1.0f;
#pragma unroll
    for (int l = 1; l <= LMAX; ++l) {
        Q[l][l] = (float)(-(2 * l - 1)) * Q[l - 1][l - 1];
        Q[l][l - 1] = (float)(2 * l - 1) * z * Q[l - 1][l - 1];
#pragma unroll
        for (int m = l - 2; m >= 0; --m) {
            Q[l][m] = ((float)(2 * l - 1) * z * Q[l - 1][m]
                       - (float)(l + m - 1) * r2 * Q[l - 2][m])
                      * (1.0f / (float)(l - m));
        }
    }

    long long nn = n;
    long long NN = N;
    emit_l<0>(out, NN, nn, Q, s, c);
    emit_l<1>(out, NN, nn, Q, s, c);
    emit_l<2>(out, NN, nn, Q, s, c);
    emit_l<3>(out, NN, nn, Q, s, c);
    emit_l<4>(out, NN, nn, Q, s, c);
    emit_l<5>(out, NN, nn, Q, s, c);
    emit_l<6>(out, NN, nn, Q, s, c);
    emit_l<7>(out, NN, nn, Q, s, c);
    emit_l<8>(out, NN, nn, Q, s, c);
}

extern "C" void kernel_launch(void* const* d_in, const int* in_sizes, int n_in,
                              void* d_out, int out_size) {
    const float* R = (const float*)d_in[0];
    float* out = (float*)d_out;
    int N = in_sizes[0] / 3;

    const int threads = 256;
    int blocks = (N + threads - 1) / threads;
    solid_harmonics_kernel<<<blocks, threads>>>(R, out, N);
}

// round 3
// speedup vs baseline: 5.0179x; 5.0179x over previous
#include <cuda_runtime.h>
#include <cuda_bf16.h>

#define LMAX 8
#define TPB 128          // points per block == threads per block
#define SMEM_FLOATS (TPB * 81)   // 10368 floats = 41,472 B (< 48 KB static limit)

// ---------------------------------------------------------------------------
// Compile-time math: factorial + Newton sqrt => normalization constants become
// SASS immediates (constexpr locals bound to template params).
// ---------------------------------------------------------------------------
__host__ __device__ constexpr double cfact(int n) {
    double r = 1.0;
    for (int i = 2; i <= n; ++i) r *= (double)i;
    return r;
}
__host__ __device__ constexpr double csqrt_(double x) {
    double g = x < 1.0 ? 1.0 : x;
    for (int i = 0; i < 100; ++i) g = 0.5 * (g + x / g);
    return g;
}
constexpr double PI_D = 3.141592653589793238462643383279502884;

__host__ __device__ constexpr float Fcoef(int l, int m) {
    double v = csqrt_(((2.0 * l + 1.0) / (2.0 * PI_D)) * (cfact(l - m) / cfact(l + m)));
    return (float)((m & 1) ? -v : v);
}
__host__ __device__ constexpr float Acoef(int l) {
    return (float)csqrt_((2.0 * l + 1.0) / (4.0 * PI_D));
}

// ---------------------------------------------------------------------------
// Emit degree-L values into the shared tile. Tile layout mirrors the block's
// gmem footprint: section l starts at float offset TPB*l*l; within it the
// tid-th point's row starts at tid*(2l+1). Odd stride => conflict-free.
// ---------------------------------------------------------------------------
template<int L, int M>
__device__ __forceinline__ void emit_ms(float* __restrict__ o,
                                        const float (&Q)[LMAX + 1][LMAX + 1],
                                        const float (&s)[LMAX + 1],
                                        const float (&c)[LMAX + 1]) {
    if constexpr (M >= 1) {
        constexpr float f = Fcoef(L, M);
        float fq = f * Q[L][M];
        o[L - M] = fq * s[M];
        o[L + M] = fq * c[M];
        emit_ms<L, M - 1>(o, Q, s, c);
    }
}

template<int L>
__device__ __forceinline__ void emit_l(float* __restrict__ smem, int tid,
                                       const float (&Q)[LMAX + 1][LMAX + 1],
                                       const float (&s)[LMAX + 1],
                                       const float (&c)[LMAX + 1]) {
    float* o = smem + TPB * (L * L) + tid * (2 * L + 1);
    constexpr float a = Acoef(L);
    o[L] = a * Q[L][0];
    emit_ms<L, L>(o, Q, s, c);
}

// ---------------------------------------------------------------------------
// Kernel: compute into registers, scatter to smem (conflict-free), then
// coalesced float4 copy smem -> gmem.
// ---------------------------------------------------------------------------
__global__ void __launch_bounds__(TPB)
solid_harmonics_kernel(const float* __restrict__ R, float* __restrict__ out, int N) {
    __shared__ float tile[SMEM_FLOATS];

    const int tid = threadIdx.x;
    const long long n0 = (long long)blockIdx.x * TPB;   // first point of this block
    const long long n = n0 + tid;
    const int P = (int)min((long long)TPB, (long long)N - n0);  // valid points

    if (n < N) {
        float x = R[3 * n + 0];
        float y = R[3 * n + 1];
        float z = R[3 * n + 2];
        float r2 = x * x + y * y + z * z;

        float c[LMAX + 1], s[LMAX + 1];
        c[0] = 1.0f;
        s[0] = 0.0f;
#pragma unroll
        for (int m = 1; m <= LMAX; ++m) {
            c[m] = x * c[m - 1] - y * s[m - 1];
            s[m] = x * s[m - 1] + y * c[m - 1];
        }

        float Q[LMAX + 1][LMAX + 1];
        Q[0][0] = 1.0f;
#pragma unroll
        for (int l = 1; l <= LMAX; ++l) {
            Q[l][l] = (float)(-(2 * l - 1)) * Q[l - 1][l - 1];
            Q[l][l - 1] = (float)(2 * l - 1) * z * Q[l - 1][l - 1];
#pragma unroll
            for (int m = l - 2; m >= 0; --m) {
                Q[l][m] = ((float)(2 * l - 1) * z * Q[l - 1][m]
                           - (float)(l + m - 1) * r2 * Q[l - 2][m])
                          * (1.0f / (float)(l - m));
            }
        }

        emit_l<0>(tile, tid, Q, s, c);
        emit_l<1>(tile, tid, Q, s, c);
        emit_l<2>(tile, tid, Q, s, c);
        emit_l<3>(tile, tid, Q, s, c);
        emit_l<4>(tile, tid, Q, s, c);
        emit_l<5>(tile, tid, Q, s, c);
        emit_l<6>(tile, tid, Q, s, c);
        emit_l<7>(tile, tid, Q, s, c);
        emit_l<8>(tile, tid, Q, s, c);
    }

    __syncthreads();

    const long long NN = N;
    if (P == TPB) {
        // Full block: vectorized, fully coalesced copy.
        // Bases: out + l*l*N + n0*(2l+1). N % 4 == 0 and n0 % TPB == 0
        // guarantee 16B alignment of every section base.
#pragma unroll
        for (int l = 0; l <= LMAX; ++l) {
            const int w = 2 * l + 1;
            const float4* src = reinterpret_cast<const float4*>(tile + TPB * l * l);
            float4* dst = reinterpret_cast<float4*>(out + (long long)(l * l) * NN + n0 * w);
            const int cnt4 = (TPB * w) / 4;   // 32*(2l+1)
            for (int j = tid; j < cnt4; j += TPB) {
                dst[j] = src[j];
            }
        }
    } else {
        // Tail block: scalar copy of the valid prefix of each section.
#pragma unroll
        for (int l = 0; l <= LMAX; ++l) {
            const int w = 2 * l + 1;
            const float* src = tile + TPB * l * l;
            float* dst = out + (long long)(l * l) * NN + n0 * w;
            const int cnt = P * w;
            for (int j = tid; j < cnt; j += TPB) {
                dst[j] = src[j];
            }
        }
    }
}

extern "C" void kernel_launch(void* const* d_in, const int* in_sizes, int n_in,
                              void* d_out, int out_size) {
    const float* R = (const float*)d_in[0];
    float* out = (float*)d_out;
    int N = in_sizes[0] / 3;

    int blocks = (N + TPB - 1) / TPB;
    solid_harmonics_kernel<<<blocks, TPB>>>(R, out, N);
}

// round 6
// speedup vs baseline: 5.3788x; 1.0719x over previous
#include <cuda_runtime.h>
#include <cuda_bf16.h>

#define LMAX 8
#define TPB 128
// Phase buffer: widest phase is {l=7,8} -> 15+17 = 32 floats per point.
#define BUF_FLOATS (TPB * 32)   // 16 KB

// ---------------------------------------------------------------------------
// Compile-time constants (constexpr Newton sqrt -> SASS immediates).
// ---------------------------------------------------------------------------
__host__ __device__ constexpr double cfact(int n) {
    double r = 1.0;
    for (int i = 2; i <= n; ++i) r *= (double)i;
    return r;
}
__host__ __device__ constexpr double csqrt_(double x) {
    double g = x < 1.0 ? 1.0 : x;
    for (int i = 0; i < 100; ++i) g = 0.5 * (g + x / g);
    return g;
}
constexpr double PI_D = 3.141592653589793238462643383279502884;

__host__ __device__ constexpr float Fcoef(int l, int m) {
    double v = csqrt_(((2.0 * l + 1.0) / (2.0 * PI_D)) * (cfact(l - m) / cfact(l + m)));
    return (float)((m & 1) ? -v : v);
}
__host__ __device__ constexpr float Acoef(int l) {
    return (float)csqrt_((2.0 * l + 1.0) / (4.0 * PI_D));
}

// ---------------------------------------------------------------------------
// Emit section L into the phase buffer at float offset TPB*OFF, point row at
// tid*(2L+1). Odd stride -> conflict-free STS.
// ---------------------------------------------------------------------------
template<int L, int M>
__device__ __forceinline__ void emit_ms(float* __restrict__ o,
                                        const float (&Q)[LMAX + 1][LMAX + 1],
                                        const float (&s)[LMAX + 1],
                                        const float (&c)[LMAX + 1]) {
    if constexpr (M >= 1) {
        constexpr float f = Fcoef(L, M);
        float fq = f * Q[L][M];
        o[L - M] = fq * s[M];
        o[L + M] = fq * c[M];
        emit_ms<L, M - 1>(o, Q, s, c);
    }
}

template<int L, int OFF>
__device__ __forceinline__ void emit_sec(float* __restrict__ tile, int tid,
                                         const float (&Q)[LMAX + 1][LMAX + 1],
                                         const float (&s)[LMAX + 1],
                                         const float (&c)[LMAX + 1]) {
    float* o = tile + TPB * OFF + tid * (2 * L + 1);
    constexpr float a = Acoef(L);
    o[L] = a * Q[L][0];
    emit_ms<L, L>(o, Q, s, c);
}

// Coalesced float4 copy of section L from the phase buffer to gmem.
template<int L, int OFF>
__device__ __forceinline__ void copy_sec_full(const float* __restrict__ tile,
                                              float* __restrict__ out,
                                              long long N, long long n0, int tid) {
    constexpr int w = 2 * L + 1;
    const float4* src = reinterpret_cast<const float4*>(tile + TPB * OFF);
    float4* dst = reinterpret_cast<float4*>(out + (long long)(L * L) * N + n0 * w);
    constexpr int cnt4 = TPB * w / 4;
    for (int j = tid; j < cnt4; j += TPB) dst[j] = src[j];
}

template<int L, int OFF>
__device__ __forceinline__ void copy_sec_tail(const float* __restrict__ tile,
                                              float* __restrict__ out,
                                              long long N, long long n0, int tid, int P) {
    constexpr int w = 2 * L + 1;
    const float* src = tile + TPB * OFF;
    float* dst = out + (long long)(L * L) * N + n0 * w;
    const int cnt = P * w;
    for (int j = tid; j < cnt; j += TPB) dst[j] = src[j];
}

// ---------------------------------------------------------------------------
// Kernel
// ---------------------------------------------------------------------------
__global__ void __launch_bounds__(TPB)
solid_harmonics_kernel(const float* __restrict__ R, float* __restrict__ out, int N) {
    __shared__ float tile[BUF_FLOATS];

    const int tid = threadIdx.x;
    const long long n0 = (long long)blockIdx.x * TPB;
    const long long n = n0 + tid;
    const int P = (int)min((long long)TPB, (long long)N - n0);
    const long long NN = N;
    const bool valid = (n < (long long)N);
    const bool full = (P == TPB);

    float c[LMAX + 1], s[LMAX + 1];
    float Q[LMAX + 1][LMAX + 1];

    if (valid) {
        float x = R[3 * n + 0];
        float y = R[3 * n + 1];
        float z = R[3 * n + 2];
        float r2 = x * x + y * y + z * z;

        c[0] = 1.0f;
        s[0] = 0.0f;
#pragma unroll
        for (int m = 1; m <= LMAX; ++m) {
            c[m] = x * c[m - 1] - y * s[m - 1];
            s[m] = x * s[m - 1] + y * c[m - 1];
        }

        Q[0][0] = 1.0f;
#pragma unroll
        for (int l = 1; l <= LMAX; ++l) {
            Q[l][l] = (float)(-(2 * l - 1)) * Q[l - 1][l - 1];
            Q[l][l - 1] = (float)(2 * l - 1) * z * Q[l - 1][l - 1];
#pragma unroll
            for (int m = l - 2; m >= 0; --m) {
                Q[l][m] = ((float)(2 * l - 1) * z * Q[l - 1][m]
                           - (float)(l + m - 1) * r2 * Q[l - 2][m])
                          * (1.0f / (float)(l - m));
            }
        }

        // l = 0: constant, direct coalesced store (no smem).
        out[n] = Acoef(0);
    }

    // ---- Phase 0: l = 1..4 (widths 3,5,7,9 -> offsets 0,3,8,15) ----
    if (valid) {
        emit_sec<1, 0>(tile, tid, Q, s, c);
        emit_sec<2, 3>(tile, tid, Q, s, c);
        emit_sec<3, 8>(tile, tid, Q, s, c);
        emit_sec<4, 15>(tile, tid, Q, s, c);
    }
    __syncthreads();
    if (full) {
        copy_sec_full<1, 0>(tile, out, NN, n0, tid);
        copy_sec_full<2, 3>(tile, out, NN, n0, tid);
        copy_sec_full<3, 8>(tile, out, NN, n0, tid);
        copy_sec_full<4, 15>(tile, out, NN, n0, tid);
    } else {
        copy_sec_tail<1, 0>(tile, out, NN, n0, tid, P);
        copy_sec_tail<2, 3>(tile, out, NN, n0, tid, P);
        copy_sec_tail<3, 8>(tile, out, NN, n0, tid, P);
        copy_sec_tail<4, 15>(tile, out, NN, n0, tid, P);
    }
    __syncthreads();

    // ---- Phase 1: l = 5,6 (widths 11,13 -> offsets 0,11) ----
    if (valid) {
        emit_sec<5, 0>(tile, tid, Q, s, c);
        emit_sec<6, 11>(tile, tid, Q, s, c);
    }
    __syncthreads();
    if (full) {
        copy_sec_full<5, 0>(tile, out, NN, n0, tid);
        copy_sec_full<6, 11>(tile, out, NN, n0, tid);
    } else {
        copy_sec_tail<5, 0>(tile, out, NN, n0, tid, P);
        copy_sec_tail<6, 11>(tile, out, NN, n0, tid, P);
    }
    __syncthreads();

    // ---- Phase 2: l = 7,8 (widths 15,17 -> offsets 0,15) ----
    if (valid) {
        emit_sec<7, 0>(tile, tid, Q, s, c);
        emit_sec<8, 15>(tile, tid, Q, s, c);
    }
    __syncthreads();
    if (full) {
        copy_sec_full<7, 0>(tile, out, NN, n0, tid);
        copy_sec_full<8, 15>(tile, out, NN, n0, tid);
    } else {
        copy_sec_tail<7, 0>(tile, out, NN, n0, tid, P);
        copy_sec_tail<8, 15>(tile, out, NN, n0, tid, P);
    }
}

extern "C" void kernel_launch(void* const* d_in, const int* in_sizes, int n_in,
                              void* d_out, int out_size) {
    const float* R = (const float*)d_in[0];
    float* out = (float*)d_out;
    int N = in_sizes[0] / 3;

    int blocks = (N + TPB - 1) / TPB;
    solid_harmonics_kernel<<<blocks, TPB>>>(R, out, N);
}